// round 10
// baseline (speedup 1.0000x reference)
#include <cuda_runtime.h>
#include <cuda_bf16.h>
#include <cstdint>
#include <math.h>

// ---------------------------------------------------------------------------
// NNLS PGD step, bf16 mma.sync m16n8k16, exact identity split, BK=32:
//   pre-pass:  Abf = bf16(th1 - I) k-packed[kt32][m][32];  Ybf likewise
//   D     = Abf @ Ybf              (tensor cores; tiny operands -> tiny error)
//   new_X = relu(D + Y + weight)   (exact fp32 identity term)
//   Y_new = new_X + (k-1)/(k+2) * (new_X - X_old)
// out: [ Y_new (K*B) | new_X (K*B) | k+1 (1) | weight (K*B) ]
// ---------------------------------------------------------------------------

#define KD 1024
#define NB 8192
#define BM 128
#define BN 128
#define BK 32
#define THREADS 256
#define STAGES 4

// packed layouts: [kt32][row][32] bf16, row stride 64 B (linear in global)
__device__ __nv_bfloat16 g_Abf[KD * KD];
__device__ __nv_bfloat16 g_Ybf[KD * NB];

#define A_STAGE_B (BM * 64)               // 8192 B
#define B_STAGE_B (BN * 64)               // 8192 B
#define SMEM_BYTES (STAGES * (A_STAGE_B + B_STAGE_B))   // 65536

#define CP_ASYNC16(dst_u32, src_ptr) \
    asm volatile("cp.async.cg.shared.global [%0], [%1], 16;" :: "r"(dst_u32), "l"(src_ptr))
#define CP_COMMIT() asm volatile("cp.async.commit_group;")
#define CP_WAIT2()  asm volatile("cp.async.wait_group 2;")

#define MMA_BF16(c, a, b) \
    asm volatile("mma.sync.aligned.m16n8k16.row.col.f32.bf16.bf16.f32 " \
        "{%0,%1,%2,%3}, {%4,%5,%6,%7}, {%8,%9}, {%0,%1,%2,%3};" \
        : "+f"((c)[0]), "+f"((c)[1]), "+f"((c)[2]), "+f"((c)[3]) \
        : "r"((a)[0]), "r"((a)[1]), "r"((a)[2]), "r"((a)[3]), \
          "r"((b)[0]), "r"((b)[1]))

// smem swizzle: 16B chunk `seg` of row -> phys chunk
//   phys = seg ^ (row & 3) ^ ((row >> 2) & 1)
// Fragment LDS (fixed seg, lq; rows lr=0..7): banks
//   16*(r&1) + 4*(seg^(r&3)^((r>>2)&1)) + lq  -- all 32 lanes distinct. CF.
__device__ __forceinline__ int swz(int row, int seg) {
    return (seg ^ (row & 3) ^ ((row >> 2) & 1)) << 4;
}

// ---------------- pre-pass: A' = bf16(th1 - I), k-packed 32 ----------------
__global__ void convA(const float* __restrict__ A)
{
    int idx = blockIdx.x * blockDim.x + threadIdx.x;    // KD*KD/8 chunks
    int m  = idx >> 7;
    int k0 = (idx & 127) * 8;
    float4 v0 = *reinterpret_cast<const float4*>(&A[(long long)m * KD + k0]);
    float4 v1 = *reinterpret_cast<const float4*>(&A[(long long)m * KD + k0 + 4]);
    if (m - k0 >= 0 && m - k0 < 8) {
        float* f = (m - k0 < 4) ? &v0.x : &v1.x;
        f[(m - k0) & 3] -= 1.0f;
    }
    uint32_t u[4];
    { __nv_bfloat162 p = __floats2bfloat162_rn(v0.x, v0.y); u[0] = *reinterpret_cast<uint32_t*>(&p); }
    { __nv_bfloat162 p = __floats2bfloat162_rn(v0.z, v0.w); u[1] = *reinterpret_cast<uint32_t*>(&p); }
    { __nv_bfloat162 p = __floats2bfloat162_rn(v1.x, v1.y); u[2] = *reinterpret_cast<uint32_t*>(&p); }
    { __nv_bfloat162 p = __floats2bfloat162_rn(v1.z, v1.w); u[3] = *reinterpret_cast<uint32_t*>(&p); }
    int kt = k0 >> 5, kk = k0 & 31;
    *reinterpret_cast<uint4*>(&g_Abf[(long long)kt * (KD * 32) + m * 32 + kk]) =
        make_uint4(u[0], u[1], u[2], u[3]);
}

// ---------------- pre-pass: Y' = bf16(Y), transposed to [kt32][n][32] ------
__global__ void convY(const float* __restrict__ Y)
{
    __shared__ __nv_bfloat16 sm[128][18];
    const int t   = threadIdx.x;
    const int kt16 = blockIdx.y;          // 16-k group
    const int nb  = blockIdx.x;
    const int r   = t >> 4;               // 0..15  k within 16-group
    const int cg  = t & 15;               // 16 col-groups of 8
    const float* src = Y + (long long)(kt16 * 16 + r) * NB + nb * 128 + cg * 8;
    float4 a = *reinterpret_cast<const float4*>(src);
    float4 b = *reinterpret_cast<const float4*>(src + 4);
    const int n = cg * 8;
    sm[n + 0][r] = __float2bfloat16_rn(a.x);
    sm[n + 1][r] = __float2bfloat16_rn(a.y);
    sm[n + 2][r] = __float2bfloat16_rn(a.z);
    sm[n + 3][r] = __float2bfloat16_rn(a.w);
    sm[n + 4][r] = __float2bfloat16_rn(b.x);
    sm[n + 5][r] = __float2bfloat16_rn(b.y);
    sm[n + 6][r] = __float2bfloat16_rn(b.z);
    sm[n + 7][r] = __float2bfloat16_rn(b.w);
    __syncthreads();
    const int nn = t >> 1, half = t & 1;  // half = 8-k subgroup
    uint32_t u[4];
    #pragma unroll
    for (int j = 0; j < 4; j++) {
        __nv_bfloat162 p;
        p.x = sm[nn][half * 8 + 2 * j];
        p.y = sm[nn][half * 8 + 2 * j + 1];
        u[j] = *reinterpret_cast<uint32_t*>(&p);
    }
    const int kt32 = kt16 >> 1, h16 = kt16 & 1;
    *reinterpret_cast<uint4*>(
        &g_Ybf[(long long)kt32 * (NB * 32) + (nb * 128 + nn) * 32 + h16 * 16 + half * 8]) =
        make_uint4(u[0], u[1], u[2], u[3]);
}

// ---------------- main GEMM ----------------
__global__ __launch_bounds__(THREADS, 2)
void nnls_bf16_kernel(const float* __restrict__ Y,
                      const float* __restrict__ Xold,
                      const int*   __restrict__ kptr,
                      const float* __restrict__ W,
                      float*       __restrict__ out,
                      int Kd, int N)
{
    extern __shared__ __align__(16) char smem[];
    char* sA = smem;                           // STAGES * 8KB
    char* sB = smem + STAGES * A_STAGE_B;      // STAGES * 8KB

    const int tid    = threadIdx.x;
    const int wid    = tid >> 5;
    const int lane   = tid & 31;
    const int lr     = lane >> 2;
    const int lq     = lane & 3;
    const int warp_m = wid & 3;       // 4 warps along M (32 rows)
    const int warp_n = wid >> 2;      // 2 warps along N (64 cols)
    const int m0     = blockIdx.x * BM;
    const int n0     = blockIdx.y * BN;
    const int NS     = Kd / BK;       // 32

    // cp.async: 2 chunks of A + 2 of B per thread per tile
    const int crow = tid >> 1;                  // 0..127
    const int cc0  = (tid & 1) * 2;             // logical chunks cc0, cc0+1
    const char* srcA = reinterpret_cast<const char*>(g_Abf)
                     + ((long long)(m0 + crow) * 64 + cc0 * 16);
    const char* srcB = reinterpret_cast<const char*>(g_Ybf)
                     + ((long long)(n0 + crow) * 64 + cc0 * 16);
    const uint32_t dstA0 = (uint32_t)__cvta_generic_to_shared(sA + crow * 64 + swz(crow, cc0));
    const uint32_t dstA1 = (uint32_t)__cvta_generic_to_shared(sA + crow * 64 + swz(crow, cc0 + 1));
    const uint32_t dstB0 = (uint32_t)__cvta_generic_to_shared(sB + crow * 64 + swz(crow, cc0));
    const uint32_t dstB1 = (uint32_t)__cvta_generic_to_shared(sB + crow * 64 + swz(crow, cc0 + 1));
    const long long tileA = (long long)Kd * 64;   // bytes per k32-tile of A'
    const long long tileB = (long long)N  * 64;

    auto issue_tile = [&](int t) {
        const int stg = t & (STAGES - 1);
        const long long oa = (long long)t * tileA;
        const long long ob = (long long)t * tileB;
        CP_ASYNC16(dstA0 + stg * A_STAGE_B, srcA + oa);
        CP_ASYNC16(dstA1 + stg * A_STAGE_B, srcA + oa + 16);
        CP_ASYNC16(dstB0 + stg * B_STAGE_B, srcB + ob);
        CP_ASYNC16(dstB1 + stg * B_STAGE_B, srcB + ob + 16);
        CP_COMMIT();
    };

    float acc[2][8][4] = {};

    issue_tile(0);
    issue_tile(1);
    issue_tile(2);

    for (int t = 0; t < NS; ++t) {
        const int stg = t & (STAGES - 1);
        CP_WAIT2();
        __syncthreads();
        if (t + 3 < NS) issue_tile(t + 3);

        const char* a_t = sA + stg * A_STAGE_B;
        const char* b_t = sB + stg * B_STAGE_B;

        #pragma unroll
        for (int kk = 0; kk < 2; kk++) {
            const int s0 = kk * 2, s1 = kk * 2 + 1;
            uint32_t bfr[8][2], afr[2][4];
            #pragma unroll
            for (int nt = 0; nt < 8; nt++) {
                const int n = warp_n * 64 + nt * 8 + lr;
                const char* bp = b_t + n * 64 + 4 * lq;
                bfr[nt][0] = *reinterpret_cast<const uint32_t*>(bp + swz(n, s0));
                bfr[nt][1] = *reinterpret_cast<const uint32_t*>(bp + swz(n, s1));
            }
            #pragma unroll
            for (int mt = 0; mt < 2; mt++) {
                const int row = warp_m * 32 + mt * 16 + lr;
                const char* ap = a_t + row * 64 + 4 * lq;
                const char* ap8 = ap + 8 * 64;
                afr[mt][0] = *reinterpret_cast<const uint32_t*>(ap  + swz(row, s0));
                afr[mt][1] = *reinterpret_cast<const uint32_t*>(ap8 + swz(row + 8, s0));
                afr[mt][2] = *reinterpret_cast<const uint32_t*>(ap  + swz(row, s1));
                afr[mt][3] = *reinterpret_cast<const uint32_t*>(ap8 + swz(row + 8, s1));
            }
            #pragma unroll
            for (int mt = 0; mt < 2; mt++)
                #pragma unroll
                for (int nt = 0; nt < 8; nt++)
                    MMA_BF16(acc[mt][nt], afr[mt], bfr[nt]);
        }
        __syncthreads();
    }

    // ---------------- fused epilogue ----------------
    const long long KN = (long long)Kd * N;
    const float kf  = (float)kptr[0];
    const float mom = (kf - 1.0f) / (kf + 2.0f);

    #pragma unroll
    for (int mt = 0; mt < 2; mt++) {
        #pragma unroll
        for (int i = 0; i < 2; i++) {
            const int row = m0 + warp_m * 32 + mt * 16 + lr + i * 8;
            #pragma unroll
            for (int nt = 0; nt < 8; nt++) {
                const int col = n0 + warp_n * 64 + nt * 8 + lq * 2;
                const long long gi = (long long)row * N + col;
                float2 y2  = *reinterpret_cast<const float2*>(&Y[gi]);
                float2 w2  = *reinterpret_cast<const float2*>(&W[gi]);
                float2 xo2 = *reinterpret_cast<const float2*>(&Xold[gi]);
                float d0 = acc[mt][nt][i * 2 + 0] + y2.x + w2.x;
                float d1 = acc[mt][nt][i * 2 + 1] + y2.y + w2.y;
                float nx0 = fmaxf(d0, 0.0f);
                float nx1 = fmaxf(d1, 0.0f);
                float2 yn, nx;
                nx.x = nx0; nx.y = nx1;
                yn.x = nx0 + mom * (nx0 - xo2.x);
                yn.y = nx1 + mom * (nx1 - xo2.y);
                *reinterpret_cast<float2*>(&out[gi])      = yn;  // Y_new
                *reinterpret_cast<float2*>(&out[KN + gi]) = nx;  // new_X
                out[2 * KN + 1 + gi]     = w2.x;                 // weight copy
                out[2 * KN + 1 + gi + 1] = w2.y;
            }
        }
    }
    if (m0 == 0 && n0 == 0 && tid == 0) out[2 * KN] = kf + 1.0f;
}

extern "C" void kernel_launch(void* const* d_in, const int* in_sizes, int n_in,
                              void* d_out, int out_size)
{
    const float* th1  = (const float*)d_in[0];
    const float* Y    = (const float*)d_in[1];
    const float* Xold = (const float*)d_in[2];
    const int*   kptr = (const int*)  d_in[3];
    const float* W    = (const float*)d_in[4];
    float* out = (float*)d_out;

    int Kd = (int)lround(sqrt((double)in_sizes[0]));   // 1024
    int N  = in_sizes[1] / Kd;                         // 8192

    static int smem_set = 0;
    if (!smem_set) {
        cudaFuncSetAttribute(nnls_bf16_kernel,
                             cudaFuncAttributeMaxDynamicSharedMemorySize, SMEM_BYTES);
        smem_set = 1;
    }

    convA<<<(KD * KD / 8) / 256, 256>>>(th1);
    convY<<<dim3(NB / 128, KD / 16), 256>>>(Y);

    dim3 grid(Kd / BM, N / BN);   // (8, 64)
    nnls_bf16_kernel<<<grid, THREADS, SMEM_BYTES>>>(Y, Xold, kptr, W, out, Kd, N);
}

// round 13
// speedup vs baseline: 1.2941x; 1.2941x over previous
#include <cuda_runtime.h>
#include <cuda_bf16.h>
#include <cstdint>
#include <math.h>

// ---------------------------------------------------------------------------
// NNLS PGD step, bf16 mma.sync m16n8k16 + ldmatrix, exact identity split:
//   pre-pass:  Abf = bf16(th1 - I) k-packed[kt][m][16];  Ybf = bf16(Y) [kt][n][16]
//   D     = Abf @ Ybf              (tensor cores; tiny operands -> tiny error)
//   new_X = relu(D + Y + weight)   (exact fp32 identity term)
//   Y_new = new_X + (k-1)/(k+2) * (new_X - X_old)
// out: [ Y_new (K*B) | new_X (K*B) | k+1 (1) | weight (K*B) ]
// ---------------------------------------------------------------------------

#define KD 1024
#define NB 8192
#define BM 128
#define BN 128
#define BK 16
#define THREADS 256
#define STAGES 4
#define A_STAGE_B (BM * 32)   // 4096 B
#define B_STAGE_B (BN * 32)

__device__ __nv_bfloat16 g_Abf[KD * KD];
__device__ __nv_bfloat16 g_Ybf[KD * NB];

#define CP_ASYNC16(dst_u32, src_ptr) \
    asm volatile("cp.async.cg.shared.global [%0], [%1], 16;" :: "r"(dst_u32), "l"(src_ptr))
#define CP_COMMIT() asm volatile("cp.async.commit_group;")
#define CP_WAIT2()  asm volatile("cp.async.wait_group 2;")

#define MMA_BF16(c, a, b) \
    asm volatile("mma.sync.aligned.m16n8k16.row.col.f32.bf16.bf16.f32 " \
        "{%0,%1,%2,%3}, {%4,%5,%6,%7}, {%8,%9}, {%0,%1,%2,%3};" \
        : "+f"((c)[0]), "+f"((c)[1]), "+f"((c)[2]), "+f"((c)[3]) \
        : "r"((a)[0]), "r"((a)[1]), "r"((a)[2]), "r"((a)[3]), \
          "r"((b)[0]), "r"((b)[1]))

// volatile + memory clobber: MUST NOT be CSE'd or moved across barriers /
// cp.async waits (stage addresses repeat every STAGES iterations!)
#define LDSM4(r0, r1, r2, r3, addr) \
    asm volatile("ldmatrix.sync.aligned.m8n8.x4.shared.b16 {%0,%1,%2,%3}, [%4];" \
        : "=r"(r0), "=r"(r1), "=r"(r2), "=r"(r3) : "r"(addr) : "memory")

// chunk swizzle within 32B row: phys16B = chunk ^ ((row>>2)&1)
__device__ __forceinline__ uint32_t rowoff(int row, int chunk) {
    return (uint32_t)(row * 32 + ((chunk ^ ((row >> 2) & 1)) << 4));
}

// ---------------- merged pre-pass ----------------
// blocks [0,512):   A' = bf16(th1 - I), k-packed [kt][m][16]
// blocks [512,4608): Y' = bf16(Y) transposed  [kt][n][16]
__global__ void conv_pre(const float* __restrict__ A, const float* __restrict__ Y)
{
    __shared__ __nv_bfloat16 sm[128][18];
    const int t = threadIdx.x;

    if (blockIdx.x < 512) {
        int idx = blockIdx.x * 256 + t;       // KD*KD/8 chunks
        int m  = idx >> 7;
        int k0 = (idx & 127) * 8;
        float4 v0 = *reinterpret_cast<const float4*>(&A[(long long)m * KD + k0]);
        float4 v1 = *reinterpret_cast<const float4*>(&A[(long long)m * KD + k0 + 4]);
        if (m - k0 >= 0 && m - k0 < 8) {
            float* f = (m - k0 < 4) ? &v0.x : &v1.x;
            f[(m - k0) & 3] -= 1.0f;
        }
        uint32_t u[4];
        { __nv_bfloat162 p = __floats2bfloat162_rn(v0.x, v0.y); u[0] = *reinterpret_cast<uint32_t*>(&p); }
        { __nv_bfloat162 p = __floats2bfloat162_rn(v0.z, v0.w); u[1] = *reinterpret_cast<uint32_t*>(&p); }
        { __nv_bfloat162 p = __floats2bfloat162_rn(v1.x, v1.y); u[2] = *reinterpret_cast<uint32_t*>(&p); }
        { __nv_bfloat162 p = __floats2bfloat162_rn(v1.z, v1.w); u[3] = *reinterpret_cast<uint32_t*>(&p); }
        int kt = k0 >> 4, kk = k0 & 15;
        *reinterpret_cast<uint4*>(&g_Abf[(long long)kt * (KD * 16) + m * 16 + kk]) =
            make_uint4(u[0], u[1], u[2], u[3]);
    } else {
        const int bid = blockIdx.x - 512;
        const int nb  = bid & 63;           // 64 n-blocks of 128
        const int kt  = bid >> 6;           // 64 k-tiles of 16
        const int r   = t >> 4;             // 0..15
        const int cg  = t & 15;
        const float* src = Y + (long long)(kt * 16 + r) * NB + nb * 128 + cg * 8;
        float4 a = *reinterpret_cast<const float4*>(src);
        float4 b = *reinterpret_cast<const float4*>(src + 4);
        const int n = cg * 8;
        sm[n + 0][r] = __float2bfloat16_rn(a.x);
        sm[n + 1][r] = __float2bfloat16_rn(a.y);
        sm[n + 2][r] = __float2bfloat16_rn(a.z);
        sm[n + 3][r] = __float2bfloat16_rn(a.w);
        sm[n + 4][r] = __float2bfloat16_rn(b.x);
        sm[n + 5][r] = __float2bfloat16_rn(b.y);
        sm[n + 6][r] = __float2bfloat16_rn(b.z);
        sm[n + 7][r] = __float2bfloat16_rn(b.w);
        __syncthreads();
        const int nn = t >> 1, half = t & 1;
        uint32_t u[4];
        #pragma unroll
        for (int j = 0; j < 4; j++) {
            __nv_bfloat162 p;
            p.x = sm[nn][half * 8 + 2 * j];
            p.y = sm[nn][half * 8 + 2 * j + 1];
            u[j] = *reinterpret_cast<uint32_t*>(&p);
        }
        *reinterpret_cast<uint4*>(
            &g_Ybf[(long long)kt * (NB * 16) + (nb * 128 + nn) * 16 + half * 8]) =
            make_uint4(u[0], u[1], u[2], u[3]);
    }
}

// ---------------- main GEMM ----------------
__global__ __launch_bounds__(THREADS, 2)
void nnls_bf16_kernel(const float* __restrict__ Y,
                      const float* __restrict__ Xold,
                      const int*   __restrict__ kptr,
                      const float* __restrict__ W,
                      float*       __restrict__ out,
                      int Kd, int N)
{
    __shared__ __align__(16) char sA[STAGES][A_STAGE_B];
    __shared__ __align__(16) char sB[STAGES][B_STAGE_B];

    const int tid    = threadIdx.x;
    const int wid    = tid >> 5;
    const int lane   = tid & 31;
    const int lr     = lane >> 2;
    const int lq     = lane & 3;
    const int warp_m = wid & 3;       // 4 warps along M (32 rows)
    const int warp_n = wid >> 2;      // 2 warps along N (64 cols)
    const int m0     = blockIdx.x * BM;
    const int n0     = blockIdx.y * BN;
    const int NS     = Kd / BK;       // 64

    // ---- cp.async mapping (1 chunk A + 1 chunk B per thread per tile) ----
    const int crow = tid >> 1;
    const int cch  = tid & 1;
    const char* srcA = reinterpret_cast<const char*>(g_Abf)
                     + ((long long)(m0 + crow) * 32 + cch * 16);
    const char* srcB = reinterpret_cast<const char*>(g_Ybf)
                     + ((long long)(n0 + crow) * 32 + cch * 16);
    const uint32_t dstA = (uint32_t)__cvta_generic_to_shared(sA[0]) + rowoff(crow, cch);
    const uint32_t dstB = (uint32_t)__cvta_generic_to_shared(sB[0]) + rowoff(crow, cch);
    const long long tileA = (long long)Kd * 32;
    const long long tileB = (long long)N  * 32;

    auto issue_tile = [&](int t) {
        const int stg = t & (STAGES - 1);
        CP_ASYNC16(dstA + stg * A_STAGE_B, srcA + (long long)t * tileA);
        CP_ASYNC16(dstB + stg * B_STAGE_B, srcB + (long long)t * tileB);
        CP_COMMIT();
    };

    // ---- ldmatrix per-lane offsets (stage-invariant) ----
    const int g  = lane >> 3;   // matrix index within x4
    const int l8 = lane & 7;
    // A x4: matrices = [rows0-7,k0-7],[rows8-15,k0-7],[rows0-7,k8-15],[rows8-15,k8-15]
    const int a_row_in = (g & 1) * 8 + l8;
    const int a_chunk  = g >> 1;
    uint32_t offA[2];
    #pragma unroll
    for (int mt = 0; mt < 2; mt++)
        offA[mt] = rowoff(warp_m * 32 + mt * 16 + a_row_in, a_chunk);
    // B x4: matrices = [n0-7,k0-7],[n0-7,k8-15],[n8-15,k0-7],[n8-15,k8-15]
    const int b_row_in = (g >> 1) * 8 + l8;
    const int b_chunk  = g & 1;
    uint32_t offB[4];
    #pragma unroll
    for (int np = 0; np < 4; np++)
        offB[np] = rowoff(warp_n * 64 + np * 16 + b_row_in, b_chunk);

    const uint32_t baseA = (uint32_t)__cvta_generic_to_shared(sA[0]);
    const uint32_t baseB = (uint32_t)__cvta_generic_to_shared(sB[0]);

    float acc[2][8][4] = {};

    issue_tile(0);
    issue_tile(1);
    issue_tile(2);

    for (int t = 0; t < NS; ++t) {
        const int stg = t & (STAGES - 1);
        CP_WAIT2();
        __syncthreads();
        if (t + 3 < NS) issue_tile(t + 3);

        const uint32_t aS = baseA + stg * A_STAGE_B;
        const uint32_t bS = baseB + stg * B_STAGE_B;

        uint32_t afr[2][4], bfr[8][2];
        #pragma unroll
        for (int mt = 0; mt < 2; mt++)
            LDSM4(afr[mt][0], afr[mt][1], afr[mt][2], afr[mt][3], aS + offA[mt]);
        #pragma unroll
        for (int np = 0; np < 4; np++)
            LDSM4(bfr[2 * np][0], bfr[2 * np][1], bfr[2 * np + 1][0], bfr[2 * np + 1][1],
                  bS + offB[np]);

        #pragma unroll
        for (int mt = 0; mt < 2; mt++)
            #pragma unroll
            for (int nt = 0; nt < 8; nt++)
                MMA_BF16(acc[mt][nt], afr[mt], bfr[nt]);
        __syncthreads();   // stage reuse guard (ldmatrix fully drained)
    }

    // ---------------- fused epilogue ----------------
    const long long KN = (long long)Kd * N;
    const float kf  = (float)kptr[0];
    const float mom = (kf - 1.0f) / (kf + 2.0f);

    #pragma unroll
    for (int mt = 0; mt < 2; mt++) {
        #pragma unroll
        for (int i = 0; i < 2; i++) {
            const int row = m0 + warp_m * 32 + mt * 16 + lr + i * 8;
            #pragma unroll
            for (int nt = 0; nt < 8; nt++) {
                const int col = n0 + warp_n * 64 + nt * 8 + lq * 2;
                const long long gi = (long long)row * N + col;
                float2 y2  = *reinterpret_cast<const float2*>(&Y[gi]);
                float2 w2  = *reinterpret_cast<const float2*>(&W[gi]);
                float2 xo2 = *reinterpret_cast<const float2*>(&Xold[gi]);
                float d0 = acc[mt][nt][i * 2 + 0] + y2.x + w2.x;
                float d1 = acc[mt][nt][i * 2 + 1] + y2.y + w2.y;
                float nx0 = fmaxf(d0, 0.0f);
                float nx1 = fmaxf(d1, 0.0f);
                float2 yn, nx;
                nx.x = nx0; nx.y = nx1;
                yn.x = nx0 + mom * (nx0 - xo2.x);
                yn.y = nx1 + mom * (nx1 - xo2.y);
                *reinterpret_cast<float2*>(&out[gi])      = yn;  // Y_new
                *reinterpret_cast<float2*>(&out[KN + gi]) = nx;  // new_X
                out[2 * KN + 1 + gi]     = w2.x;                 // weight copy
                out[2 * KN + 1 + gi + 1] = w2.y;
            }
        }
    }
    if (m0 == 0 && n0 == 0 && tid == 0) out[2 * KN] = kf + 1.0f;
}

extern "C" void kernel_launch(void* const* d_in, const int* in_sizes, int n_in,
                              void* d_out, int out_size)
{
    const float* th1  = (const float*)d_in[0];
    const float* Y    = (const float*)d_in[1];
    const float* Xold = (const float*)d_in[2];
    const int*   kptr = (const int*)  d_in[3];
    const float* W    = (const float*)d_in[4];
    float* out = (float*)d_out;

    int Kd = (int)lround(sqrt((double)in_sizes[0]));   // 1024
    int N  = in_sizes[1] / Kd;                         // 8192

    conv_pre<<<512 + (NB / 128) * (KD / 16), 256>>>(th1, Y);

    dim3 grid(Kd / BM, N / BN);   // (8, 64)
    nnls_bf16_kernel<<<grid, THREADS>>>(Y, Xold, kptr, W, out, Kd, N);
}